// round 3
// baseline (speedup 1.0000x reference)
#include <cuda_runtime.h>
#include <cuda_fp16.h>
#include <cuda_bf16.h>
#include <cstdint>

// Problem constants
#define M_TOT 256
#define N_TOT 16384
#define K_TOT 4096
#define G_TOT (16384 * 4096 / 16)  // 4194304 groups
// Tiling
#define M_TILE 128
#define N_TILE 256
#define K_CHUNK 64
#define NCHUNK (K_TOT / K_CHUNK)   // 64
#define THREADS 512
#define K_PAD 72                   // halves per row

#define A_HALVES (M_TILE * K_PAD)            // 9216
#define B_HALVES (N_TILE * K_PAD)            // 18432
#define BUF_HALVES (A_HALVES + B_HALVES)     // 27648
#define SMEM_BYTES (BUF_HALVES * 2 * 2)      // 110592 (double buffered)

// Scratch: pre-divided norms (norm/3) in fp32. 16 MB static device array.
__device__ float g_cnorm[G_TOT];
__device__ int   g_norm_dtype;   // 0=fp32, 1=fp16, 2=bf16

// ---------------------------------------------------------------------------
// Detect the storage dtype of the weight_norm buffer. Values are U(0,1).
//  - fp16 data read as fp16: all in (1e-6,1), max > 0.1
//  - bf16 data read as fp16: ~1.5..2.0 (rejected); as bf16: U(0,1) (accepted)
//  - fp32 data read as fp16/bf16 at even idx: low-mantissa garbage (rejected)
// ---------------------------------------------------------------------------
__global__ void detect_norm_dtype(const void* __restrict__ p)
{
    const __half*         ph = (const __half*)p;
    const __nv_bfloat16*  pb = (const __nv_bfloat16*)p;
    bool ok_h = true, ok_b = true;
    float mx_h = 0.f, mx_b = 0.f;
    for (int i = 0; i < 256; i++) {
        float vh = __half2float(ph[i]);
        float vb = __bfloat162float(pb[i]);
        if (!(vh > 1e-6f && vh < 1.0f)) ok_h = false;
        if (!(vb > 1e-6f && vb < 1.0f)) ok_b = false;
        if (vh == vh && vh > mx_h) mx_h = vh;
        if (vb == vb && vb > mx_b) mx_b = vb;
    }
    int f = 0;
    if (ok_h && mx_h > 0.1f)      f = 1;
    else if (ok_b && mx_b > 0.1f) f = 2;
    g_norm_dtype = f;
}

__global__ void convert_norms(const void* __restrict__ p)
{
    int g = blockIdx.x * blockDim.x + threadIdx.x;
    if (g >= G_TOT) return;
    int f = g_norm_dtype;
    float v;
    if (f == 1)      v = __half2float(((const __half*)p)[g]);
    else if (f == 2) v = __bfloat162float(((const __nv_bfloat16*)p)[g]);
    else             v = ((const float*)p)[g];
    g_cnorm[g] = v * (1.0f / 3.0f);
}

// ---------------------------------------------------------------------------
// Main GEMM kernel
// ---------------------------------------------------------------------------
__global__ __launch_bounds__(THREADS, 1)
void linear2bit_kernel(const float* __restrict__ x,
                       const int4* __restrict__ wq,      // [G] groups of 4 int32
                       const float* __restrict__ cnorm,  // [G] = norm/3, fp32
                       const float* __restrict__ bias,   // [N_TOT]
                       float* __restrict__ out)          // [M_TOT, N_TOT]
{
    extern __shared__ __half sm[];
    __half* Abuf[2];
    __half* Bbuf[2];
    Abuf[0] = sm;
    Bbuf[0] = sm + A_HALVES;
    Abuf[1] = sm + BUF_HALVES;
    Bbuf[1] = Abuf[1] + A_HALVES;

    const int tid   = threadIdx.x;
    const int lane  = tid & 31;
    const int warp  = tid >> 5;
    const int warp_m = warp >> 2;   // 0..3  (32 M rows each)
    const int warp_n = warp & 3;    // 0..3  (64 N cols each)
    const int noff = blockIdx.x * N_TILE;
    const int moff = blockIdx.y * M_TILE;

    float acc[2][8][4];
#pragma unroll
    for (int i = 0; i < 2; i++)
#pragma unroll
        for (int j = 0; j < 8; j++)
#pragma unroll
            for (int r = 0; r < 4; r++) acc[i][j][r] = 0.f;

    const int xc4 = tid & 15;       // float4 col within chunk
    const int xr0 = tid >> 4;       // 0..31; rows xr0 + p*32
    float4 xr[4];
    int4   qr[2];
    float  nr[2];

    // ---- preload chunk 0
    {
        const float4* xg = (const float4*)x;
#pragma unroll
        for (int p = 0; p < 4; p++) {
            int row = moff + xr0 + p * 32;
            xr[p] = xg[(size_t)row * (K_TOT / 4) + xc4];
        }
#pragma unroll
        for (int h = 0; h < 2; h++) {
            int gl  = tid + h * 512;
            int wn  = gl >> 2;
            int wgi = gl & 3;
            int g   = (noff + wn) * (K_TOT / 16) + wgi;
            qr[h] = wq[g];
            nr[h] = cnorm[g];
        }
    }

    int pb = 0;
    for (int c = 0; c < NCHUNK; ++c) {
        __half* A = Abuf[pb];
        __half* B = Bbuf[pb];

        // ---- store staged regs to smem
#pragma unroll
        for (int p = 0; p < 4; p++) {
            int row = xr0 + p * 32;
            __half2* dst = (__half2*)(A + row * K_PAD + xc4 * 4);
            float4 v = xr[p];
            dst[0] = __floats2half2_rn(v.x, v.y);
            dst[1] = __floats2half2_rn(v.z, v.w);
        }
#pragma unroll
        for (int h = 0; h < 2; h++) {
            int gl  = tid + h * 512;
            int wn  = gl >> 2;
            int wgi = gl & 3;
            float cn = nr[h];
            __half2* dst = (__half2*)(B + wn * K_PAD + wgi * 16);
            int words[4] = {qr[h].x, qr[h].y, qr[h].z, qr[h].w};
#pragma unroll
            for (int w = 0; w < 4; w++) {
                int q = words[w];
#pragma unroll
                for (int i = 0; i < 4; i += 2) {
                    int v0 = (q >> (2 * i)) & 3;
                    int v1 = (q >> (2 * i + 2)) & 3;
                    float f0 = cn * (float)(2 * v0 - 3);
                    float f1 = cn * (float)(2 * v1 - 3);
                    dst[w * 2 + (i >> 1)] = __floats2half2_rn(f0, f1);
                }
            }
        }
        __syncthreads();

        // ---- prefetch next chunk into regs
        if (c + 1 < NCHUNK) {
            const float4* xg = (const float4*)x;
            int kc4 = (c + 1) * (K_CHUNK / 4);
#pragma unroll
            for (int p = 0; p < 4; p++) {
                int row = moff + xr0 + p * 32;
                xr[p] = xg[(size_t)row * (K_TOT / 4) + kc4 + xc4];
            }
#pragma unroll
            for (int h = 0; h < 2; h++) {
                int gl  = tid + h * 512;
                int wn  = gl >> 2;
                int wgi = gl & 3;
                int g   = (noff + wn) * (K_TOT / 16) + (c + 1) * 4 + wgi;
                qr[h] = wq[g];
                nr[h] = cnorm[g];
            }
        }

        // ---- compute: 4 k-steps of 16
        const __half* Aw = A + (warp_m * 32) * K_PAD;
        const __half* Bw = B + (warp_n * 64) * K_PAD;
#pragma unroll
        for (int ks = 0; ks < 4; ++ks) {
            int k0 = ks * 16 + (lane & 3) * 2;
            unsigned af[2][4];
#pragma unroll
            for (int mi = 0; mi < 2; mi++) {
                const __half* base = Aw + (mi * 16 + (lane >> 2)) * K_PAD;
                af[mi][0] = *(const unsigned*)(base + k0);
                af[mi][1] = *(const unsigned*)(base + 8 * K_PAD + k0);
                af[mi][2] = *(const unsigned*)(base + k0 + 8);
                af[mi][3] = *(const unsigned*)(base + 8 * K_PAD + k0 + 8);
            }
#pragma unroll
            for (int ni = 0; ni < 8; ni++) {
                const __half* base = Bw + (ni * 8 + (lane >> 2)) * K_PAD;
                unsigned b0 = *(const unsigned*)(base + k0);
                unsigned b1 = *(const unsigned*)(base + k0 + 8);
#pragma unroll
                for (int mi = 0; mi < 2; mi++) {
                    asm volatile(
                        "mma.sync.aligned.m16n8k16.row.col.f32.f16.f16.f32 "
                        "{%0,%1,%2,%3}, {%4,%5,%6,%7}, {%8,%9}, {%0,%1,%2,%3};\n"
                        : "+f"(acc[mi][ni][0]), "+f"(acc[mi][ni][1]),
                          "+f"(acc[mi][ni][2]), "+f"(acc[mi][ni][3])
                        : "r"(af[mi][0]), "r"(af[mi][1]), "r"(af[mi][2]), "r"(af[mi][3]),
                          "r"(b0), "r"(b1));
                }
            }
        }
        __syncthreads();
        pb ^= 1;
    }

    // ---- epilogue: add bias, write fp32
#pragma unroll
    for (int mi = 0; mi < 2; mi++) {
        int r = moff + warp_m * 32 + mi * 16 + (lane >> 2);
#pragma unroll
        for (int ni = 0; ni < 8; ni++) {
            int ncol = noff + warp_n * 64 + ni * 8 + (lane & 3) * 2;
            float b0 = bias[ncol];
            float b1 = bias[ncol + 1];
            float2* o0 = (float2*)(out + (size_t)r * N_TOT + ncol);
            float2* o1 = (float2*)(out + (size_t)(r + 8) * N_TOT + ncol);
            *o0 = make_float2(acc[mi][ni][0] + b0, acc[mi][ni][1] + b1);
            *o1 = make_float2(acc[mi][ni][2] + b0, acc[mi][ni][3] + b1);
        }
    }
}

extern "C" void kernel_launch(void* const* d_in, const int* in_sizes, int n_in,
                              void* d_out, int out_size)
{
    // Bind inputs by SIZE ORDER (robust whether in_sizes is elements or bytes,
    // and whatever the 16-bit norm storage is):
    //   weight_q2 (largest) > weight_norm > x > bias (smallest)
    int order[4] = {0, 1, 2, 3};
    // insertion sort descending by in_sizes
    for (int i = 1; i < 4 && i < n_in; i++) {
        int v = order[i];
        int j = i - 1;
        while (j >= 0 && (long long)in_sizes[order[j]] < (long long)in_sizes[v]) {
            order[j + 1] = order[j];
            j--;
        }
        order[j + 1] = v;
    }
    const int4*  wq    = (const int4*)d_in[order[0]];
    const void*  pnorm = d_in[order[1]];
    const float* x     = (const float*)d_in[order[2]];
    const float* bias  = (const float*)d_in[order[3]];
    float* out = (float*)d_out;

    // Prepass: detect norm dtype, convert to fp32 cnorm = norm/3.
    detect_norm_dtype<<<1, 1>>>(pnorm);
    convert_norms<<<G_TOT / 256, 256>>>(pnorm);

    float* cnorm_dev = nullptr;
    cudaGetSymbolAddress((void**)&cnorm_dev, g_cnorm);

    cudaFuncSetAttribute(linear2bit_kernel,
                         cudaFuncAttributeMaxDynamicSharedMemorySize, SMEM_BYTES);

    dim3 grid(N_TOT / N_TILE, M_TOT / M_TILE);  // (64, 2) = 128 CTAs
    linear2bit_kernel<<<grid, THREADS, SMEM_BYTES>>>(x, wq, cnorm_dev, bias, out);
}

// round 5
// speedup vs baseline: 1.3355x; 1.3355x over previous
#include <cuda_runtime.h>
#include <cuda_fp16.h>
#include <cuda_bf16.h>
#include <cstdint>

#define M_TOT 256
#define N_TOT 16384
#define K_TOT 4096
#define G_TOT (N_TOT * K_TOT / 16)   // 4194304
#define GPR   (K_TOT / 16)           // 256 groups per row

#define M_TILE 128
#define N_TILE 256
#define K_CHUNK 64
#define NCHUNK (K_TOT / K_CHUNK)     // 64
#define THREADS 512
#define K_PAD 72                     // halves per row; 144B stride = 9*16B

#define A_BYTES (M_TILE * K_PAD * 2)   // 18432
#define B_BYTES (N_TILE * K_PAD * 2)   // 36864
#define SM_A0 0
#define SM_B0 (SM_A0 + A_BYTES)
#define SM_A1 (SM_B0 + B_BYTES)
#define SM_B1 (SM_A1 + A_BYTES)
#define SMEM_BYTES (SM_B1 + B_BYTES)   // 110592

// ---------------- device scratch ----------------
__device__ float  g_cnorm[G_TOT];        // norm/3 fp32 (16 MB)
__device__ __half g_xh[M_TOT * K_TOT];   // x in fp16 (2 MB)

__device__ __forceinline__ uint32_t smem_u32(const void* p) {
    uint32_t a;
    asm("{ .reg .u64 t; cvta.to.shared.u64 t, %1; cvt.u32.u64 %0, t; }" : "=r"(a) : "l"(p));
    return a;
}
#define CP_ASYNC16(dst, src) \
    asm volatile("cp.async.cg.shared.global [%0], [%1], 16;" :: "r"(dst), "l"(src) : "memory")
#define CP_COMMIT() asm volatile("cp.async.commit_group;" ::: "memory")
#define CP_WAIT0()  asm volatile("cp.async.wait_group 0;" ::: "memory")
#define LDSM_X4(r0, r1, r2, r3, a) \
    asm volatile("ldmatrix.sync.aligned.m8n8.x4.shared.b16 {%0,%1,%2,%3}, [%4];" \
        : "=r"(r0), "=r"(r1), "=r"(r2), "=r"(r3) : "r"(a))

// ---------------- prepass ----------------
// norm dtype detect per block + convert to fp32 norm/3
__global__ void convert_norms(const uint16_t* __restrict__ p)
{
    int g = blockIdx.x * 256 + threadIdx.x;
    __half        hv = *(const __half*)&p[g];
    __nv_bfloat16 bv = *(const __nv_bfloat16*)&p[g];
    float vh = __half2float(hv);
    float vb = __bfloat162float(bv);
    bool okh = (vh > 1e-6f && vh < 1.0f);
    bool okb = (vb > 1e-6f && vb < 1.0f);
    int allh = __syncthreads_and(okh);
    int allb = __syncthreads_and(okb);
    int bigh = __syncthreads_or(okh && vh > 0.1f);
    int bigb = __syncthreads_or(okb && vb > 0.1f);
    float v;
    if (allh && bigh)      v = vh;
    else if (allb && bigb) v = vb;
    else                   v = ((const float*)p)[g];
    g_cnorm[g] = v * (1.0f / 3.0f);
}

__global__ void convert_x(const float4* __restrict__ x)
{
    int i = blockIdx.x * blockDim.x + threadIdx.x;
    float4 v = x[i];
    __half2* dst = (__half2*)&g_xh[i * 4];
    dst[0] = __floats2half2_rn(v.x, v.y);
    dst[1] = __floats2half2_rn(v.z, v.w);
}

// ---------------- main GEMM (mma.sync + ldmatrix + cp.async) ----------------
__global__ __launch_bounds__(THREADS, 1)
void l2b_hmma(const int4* __restrict__ wq,
              const float* __restrict__ cnorm,
              const __half* __restrict__ xh,
              const float* __restrict__ bias,
              float* __restrict__ out)
{
    extern __shared__ char smem[];
    const uint32_t sb = smem_u32(smem);
    const int tid  = threadIdx.x;
    const int lane = tid & 31;
    const int warp = tid >> 5;
    const int warp_m = warp >> 2;     // 0..3 : 32 M rows
    const int warp_n = warp & 3;      // 0..3 : 64 N cols
    const int noff = blockIdx.x * N_TILE;
    const int moff = blockIdx.y * M_TILE;

    float acc[2][8][4];
#pragma unroll
    for (int i = 0; i < 2; i++)
#pragma unroll
        for (int j = 0; j < 8; j++)
#pragma unroll
            for (int r = 0; r < 4; r++) acc[i][j][r] = 0.f;

    // ---- A staging: 1024 16B segs, 2 per thread: seg = tid + h*512
    // row = seg>>3 (0..127), s = seg&7
    // ---- B staging: 2 groups per thread: gl = tid + h*512; wn = gl>>2, wgi = gl&3
    int4  qr[2];
    float nr[2];

    auto issueA = [&](int c, uint32_t abase) {
#pragma unroll
        for (int h = 0; h < 2; h++) {
            int seg = tid + h * 512;
            int row = seg >> 3;
            int s   = seg & 7;
            const __half* src = xh + (size_t)(moff + row) * K_TOT + c * K_CHUNK + s * 8;
            uint32_t dst = abase + row * (K_PAD * 2) + s * 16;
            CP_ASYNC16(dst, src);
        }
        CP_COMMIT();
    };
    auto loadW = [&](int c) {
#pragma unroll
        for (int h = 0; h < 2; h++) {
            int gl  = tid + h * 512;
            int wn  = gl >> 2;
            int wgi = gl & 3;
            int g   = (noff + wn) * GPR + c * 4 + wgi;
            qr[h] = wq[g];
            nr[h] = cnorm[g];
        }
    };

    issueA(0, sb + SM_A0);
    loadW(0);

    // ---- precomputed fragment-load offsets (ldmatrix lane->row/col maps)
    // A x4: lanes0-7 rows+0-7 k0 | 8-15 rows+8-15 k0 | 16-23 rows+0-7 k0+8 | 24-31 rows+8-15 k0+8
    uint32_t aoff[2];
#pragma unroll
    for (int mi = 0; mi < 2; mi++)
        aoff[mi] = (uint32_t)(warp_m * 32 + mi * 16 + (lane & 15)) * (K_PAD * 2)
                 + ((lane >> 4) & 1) * 16;
    // B x4: lanes0-7 n+0-7 k0 | 8-15 n+0-7 k0+8 | 16-23 n+8-15 k0 | 24-31 n+8-15 k0+8
    uint32_t boff[4];
#pragma unroll
    for (int np = 0; np < 4; np++)
        boff[np] = (uint32_t)(warp_n * 64 + np * 16 + ((lane & 7) | ((lane & 16) >> 1))) * (K_PAD * 2)
                 + ((lane >> 3) & 1) * 16;

    const uint32_t MAGIC = 0x64006400u;            // half2(1024,1024)
    const __half2  magic_h2 = *(const __half2*)&MAGIC;

    for (int c = 0; c < NCHUNK; ++c) {
        const int pb = c & 1;
        const uint32_t abase = sb + (pb ? SM_A1 : SM_A0);
        const uint32_t bbase = sb + (pb ? SM_B1 : SM_B0);

        // ---- dequant + STS B(c): 2 groups, 2 x 16B stores each
#pragma unroll
        for (int h = 0; h < 2; h++) {
            int gl  = tid + h * 512;
            int wn  = gl >> 2;
            int wgi = gl & 3;
            float cn = nr[h];
            __half   tc = __float2half_rn(2.0f * cn);
            __half   m3 = __float2half_rn(-3.0f * cn);
            __half2  tc2 = __half2half2(tc);
            __half2  m32 = __half2half2(m3);
            int words[4] = {qr[h].x, qr[h].y, qr[h].z, qr[h].w};
            uint32_t hv[8];
#pragma unroll
            for (int w = 0; w < 4; w++) {
                uint32_t q = (uint32_t)words[w];
                uint32_t u01 = MAGIC | (q & 3u) | ((q & 0xCu) << 14);
                uint32_t u23 = MAGIC | ((q >> 4) & 3u) | ((q & 0xC0u) << 10);
                __half2 v01 = __hsub2(*(__half2*)&u01, magic_h2);   // exact (v0,v1)
                __half2 v23 = __hsub2(*(__half2*)&u23, magic_h2);
                __half2 w01 = __hfma2(v01, tc2, m32);
                __half2 w23 = __hfma2(v23, tc2, m32);
                hv[w * 2]     = *(uint32_t*)&w01;
                hv[w * 2 + 1] = *(uint32_t*)&w23;
            }
            uint32_t a0 = bbase + (uint32_t)wn * (K_PAD * 2) + wgi * 32;
            asm volatile("st.shared.v4.b32 [%0], {%1,%2,%3,%4};"
                :: "r"(a0), "r"(hv[0]), "r"(hv[1]), "r"(hv[2]), "r"(hv[3]) : "memory");
            asm volatile("st.shared.v4.b32 [%0], {%1,%2,%3,%4};"
                :: "r"(a0 + 16), "r"(hv[4]), "r"(hv[5]), "r"(hv[6]), "r"(hv[7]) : "memory");
        }

        CP_WAIT0();          // A(c) landed (A(c+1) not yet issued)
        __syncthreads();

        // ---- start next-chunk fetches (overlap with compute)
        if (c + 1 < NCHUNK) {
            issueA(c + 1, sb + (pb ? SM_A0 : SM_A1));
            loadW(c + 1);
        }

        // ---- compute chunk c: 4 k-steps, ldmatrix + mma
#pragma unroll
        for (int ks = 0; ks < 4; ++ks) {
            const uint32_t kb = ks * 32;
            uint32_t a0, a1, a2, a3, a4, a5, a6, a7;
            LDSM_X4(a0, a1, a2, a3, abase + aoff[0] + kb);
            LDSM_X4(a4, a5, a6, a7, abase + aoff[1] + kb);
#pragma unroll
            for (int np = 0; np < 4; np++) {
                uint32_t b0, b1, b2, b3;
                LDSM_X4(b0, b1, b2, b3, bbase + boff[np] + kb);
#pragma unroll
                for (int e = 0; e < 2; e++) {
                    int ni = np * 2 + e;
                    uint32_t bb0 = e ? b2 : b0;
                    uint32_t bb1 = e ? b3 : b1;
                    asm volatile(
                        "mma.sync.aligned.m16n8k16.row.col.f32.f16.f16.f32 "
                        "{%0,%1,%2,%3}, {%4,%5,%6,%7}, {%8,%9}, {%0,%1,%2,%3};\n"
                        : "+f"(acc[0][ni][0]), "+f"(acc[0][ni][1]),
                          "+f"(acc[0][ni][2]), "+f"(acc[0][ni][3])
                        : "r"(a0), "r"(a1), "r"(a2), "r"(a3), "r"(bb0), "r"(bb1));
                    asm volatile(
                        "mma.sync.aligned.m16n8k16.row.col.f32.f16.f16.f32 "
                        "{%0,%1,%2,%3}, {%4,%5,%6,%7}, {%8,%9}, {%0,%1,%2,%3};\n"
                        : "+f"(acc[1][ni][0]), "+f"(acc[1][ni][1]),
                          "+f"(acc[1][ni][2]), "+f"(acc[1][ni][3])
                        : "r"(a4), "r"(a5), "r"(a6), "r"(a7), "r"(bb0), "r"(bb1));
                }
            }
        }
    }

    // ---- epilogue: bias + fp32 store
#pragma unroll
    for (int mi = 0; mi < 2; mi++) {
        int r = moff + warp_m * 32 + mi * 16 + (lane >> 2);
#pragma unroll
        for (int ni = 0; ni < 8; ni++) {
            int ncol = noff + warp_n * 64 + ni * 8 + (lane & 3) * 2;
            float b0 = bias[ncol];
            float b1 = bias[ncol + 1];
            float2* o0 = (float2*)(out + (size_t)r * N_TOT + ncol);
            float2* o1 = (float2*)(out + (size_t)(r + 8) * N_TOT + ncol);
            *o0 = make_float2(acc[mi][ni][0] + b0, acc[mi][ni][1] + b1);
            *o1 = make_float2(acc[mi][ni][2] + b0, acc[mi][ni][3] + b1);
        }
    }
}

// ---------------- launcher ----------------
extern "C" void kernel_launch(void* const* d_in, const int* in_sizes, int n_in,
                              void* d_out, int out_size)
{
    // Bind by size order: wq > norm > x > bias
    int order[4] = {0, 1, 2, 3};
    for (int i = 1; i < 4 && i < n_in; i++) {
        int v = order[i], j = i - 1;
        while (j >= 0 && (long long)in_sizes[order[j]] < (long long)in_sizes[v]) {
            order[j + 1] = order[j]; j--;
        }
        order[j + 1] = v;
    }
    const int4*     wq    = (const int4*)d_in[order[0]];
    const uint16_t* pnorm = (const uint16_t*)d_in[order[1]];
    const float*    x     = (const float*)d_in[order[2]];
    const float*    bias  = (const float*)d_in[order[3]];
    float* out = (float*)d_out;

    convert_norms<<<G_TOT / 256, 256>>>(pnorm);
    convert_x<<<(M_TOT * K_TOT / 4) / 256, 256>>>((const float4*)x);

    float*  cnorm_dev = nullptr;
    __half* xh_dev    = nullptr;
    cudaGetSymbolAddress((void**)&cnorm_dev, g_cnorm);
    cudaGetSymbolAddress((void**)&xh_dev, g_xh);

    cudaFuncSetAttribute(l2b_hmma, cudaFuncAttributeMaxDynamicSharedMemorySize, SMEM_BYTES);
    dim3 grid(N_TOT / N_TILE, M_TOT / M_TILE);   // (64, 2)
    l2b_hmma<<<grid, THREADS, SMEM_BYTES>>>(wq, cnorm_dev, xh_dev, bias, out);
}

// round 6
// speedup vs baseline: 1.3555x; 1.0150x over previous
#include <cuda_runtime.h>
#include <cuda_fp16.h>
#include <cuda_bf16.h>
#include <cstdint>

#define M_TOT 256
#define N_TOT 16384
#define K_TOT 4096
#define G_TOT (N_TOT * K_TOT / 16)   // 4194304
#define GPR   (K_TOT / 16)           // 256 groups per row

#define M_TILE 128
#define N_TILE 256
#define K_CHUNK 64
#define NCHUNK (K_TOT / K_CHUNK)     // 64
#define THREADS 512
#define K_PAD 72                     // halves per row; 144B stride

#define A_BYTES (M_TILE * K_PAD * 2)   // 18432
#define B_BYTES (N_TILE * K_PAD * 2)   // 36864
#define SM_A0 0
#define SM_B0 (SM_A0 + A_BYTES)
#define SM_A1 (SM_B0 + B_BYTES)
#define SM_B1 (SM_A1 + A_BYTES)
#define SMEM_BYTES (SM_B1 + B_BYTES)   // 110592

// prepass grid split
#define NB_NORM 2048    // 2048 * 256 * 8 = 4194304 groups
#define NB_X    512     // 512 * 256 * 8  = 1048576 floats

// ---------------- device scratch ----------------
__device__ uint32_t g_cn2[G_TOT];        // half2(2n/3, -n) per group (16 MB)
__device__ __half   g_xh[M_TOT * K_TOT]; // x in fp16 (2 MB)

__device__ __forceinline__ uint32_t smem_u32(const void* p) {
    uint32_t a;
    asm("{ .reg .u64 t; cvta.to.shared.u64 t, %1; cvt.u32.u64 %0, t; }" : "=r"(a) : "l"(p));
    return a;
}
#define CP_ASYNC16(dst, src) \
    asm volatile("cp.async.cg.shared.global [%0], [%1], 16;" :: "r"(dst), "l"(src) : "memory")
#define CP_COMMIT() asm volatile("cp.async.commit_group;" ::: "memory")
#define CP_WAIT0()  asm volatile("cp.async.wait_group 0;" ::: "memory")
#define LDSM_X4(r0, r1, r2, r3, a) \
    asm volatile("ldmatrix.sync.aligned.m8n8.x4.shared.b16 {%0,%1,%2,%3}, [%4];" \
        : "=r"(r0), "=r"(r1), "=r"(r2), "=r"(r3) : "r"(a))
// f16-accumulator mma (2 D regs of half2)
#define MMA16(d0, d1, a0, a1, a2, a3, b0, b1)                                  \
    asm volatile("mma.sync.aligned.m16n8k16.row.col.f16.f16.f16.f16 "          \
        "{%0,%1}, {%2,%3,%4,%5}, {%6,%7}, {%0,%1};\n"                          \
        : "+r"(d0), "+r"(d1)                                                   \
        : "r"(a0), "r"(a1), "r"(a2), "r"(a3), "r"(b0), "r"(b1))

// ---------------- fused prepass ----------------
// blocks [0, NB_NORM): norms -> half2(2n/3, -n); per-block dtype consensus
// blocks [NB_NORM, NB_NORM+NB_X): x fp32 -> fp16
__global__ void prepass(const uint16_t* __restrict__ pnorm,
                        const float* __restrict__ x)
{
    const int tid = threadIdx.x;
    const int b = blockIdx.x;
    if (b < NB_NORM) {
        const int base = (b * 256 + tid) * 8;
        uint4 raw = *(const uint4*)(pnorm + base);
        uint16_t h[8];
        *(uint4*)h = raw;
        float vh[8], vb[8];
        bool okh = true, okb = true, bigh = false, bigb = false;
#pragma unroll
        for (int i = 0; i < 8; i++) {
            vh[i] = __half2float(*(const __half*)&h[i]);
            vb[i] = __bfloat162float(*(const __nv_bfloat16*)&h[i]);
            okh &= (vh[i] > 1e-6f && vh[i] < 1.0f);
            okb &= (vb[i] > 1e-6f && vb[i] < 1.0f);
            bigh |= (vh[i] > 0.1f);
            bigb |= (vb[i] > 0.1f);
        }
        int allh = __syncthreads_and(okh);
        int allb = __syncthreads_and(okb);
        int anyh = __syncthreads_or(okh && bigh);
        int anyb = __syncthreads_or(okb && bigb);
        uint32_t outw[8];
        if (allh && anyh) {
#pragma unroll
            for (int i = 0; i < 8; i++) {
                __half2 o = __halves2half2(__float2half_rn(vh[i] * (2.0f / 3.0f)),
                                           __float2half_rn(-vh[i]));
                outw[i] = *(uint32_t*)&o;
            }
        } else if (allb && anyb) {
#pragma unroll
            for (int i = 0; i < 8; i++) {
                __half2 o = __halves2half2(__float2half_rn(vb[i] * (2.0f / 3.0f)),
                                           __float2half_rn(-vb[i]));
                outw[i] = *(uint32_t*)&o;
            }
        } else {
            const float* pf = (const float*)pnorm;
#pragma unroll
            for (int i = 0; i < 8; i++) {
                float v = pf[base + i];
                __half2 o = __halves2half2(__float2half_rn(v * (2.0f / 3.0f)),
                                           __float2half_rn(-v));
                outw[i] = *(uint32_t*)&o;
            }
        }
        uint32_t* dst = g_cn2 + base;
        *(uint4*)(dst)     = make_uint4(outw[0], outw[1], outw[2], outw[3]);
        *(uint4*)(dst + 4) = make_uint4(outw[4], outw[5], outw[6], outw[7]);
    } else {
        const int base = ((b - NB_NORM) * 256 + tid) * 8;
        float4 v0 = *(const float4*)(x + base);
        float4 v1 = *(const float4*)(x + base + 4);
        __half2 o[4];
        o[0] = __floats2half2_rn(v0.x, v0.y);
        o[1] = __floats2half2_rn(v0.z, v0.w);
        o[2] = __floats2half2_rn(v1.x, v1.y);
        o[3] = __floats2half2_rn(v1.z, v1.w);
        *(uint4*)(g_xh + base) = *(uint4*)o;
    }
}

// ---------------- main GEMM ----------------
__global__ __launch_bounds__(THREADS, 1)
void l2b_hmma(const int4* __restrict__ wq,
              const uint32_t* __restrict__ cn2,
              const __half* __restrict__ xh,
              const float* __restrict__ bias,
              float* __restrict__ out)
{
    extern __shared__ char smem[];
    const uint32_t sb = smem_u32(smem);
    const int tid  = threadIdx.x;
    const int lane = tid & 31;
    const int warp = tid >> 5;
    const int warp_m = warp >> 2;     // 0..3 : 32 M rows
    const int warp_n = warp & 3;      // 0..3 : 64 N cols
    const int noff = blockIdx.x * N_TILE;
    const int moff = blockIdx.y * M_TILE;

    // f32 master accumulators + f16 span accumulators
    float acc[2][8][4];
    uint32_t a16[2][8][2];
#pragma unroll
    for (int i = 0; i < 2; i++)
#pragma unroll
        for (int j = 0; j < 8; j++)
#pragma unroll
            for (int r = 0; r < 4; r++) acc[i][j][r] = 0.f;

    int4     qr[2];
    uint32_t nr[2];

    auto issueA = [&](int c, uint32_t abase) {
#pragma unroll
        for (int h = 0; h < 2; h++) {
            int seg = tid + h * 512;
            int row = seg >> 3;
            int s   = seg & 7;
            const __half* src = xh + (size_t)(moff + row) * K_TOT + c * K_CHUNK + s * 8;
            uint32_t dst = abase + row * (K_PAD * 2) + s * 16;
            CP_ASYNC16(dst, src);
        }
        CP_COMMIT();
    };
    auto loadW = [&](int c) {
#pragma unroll
        for (int h = 0; h < 2; h++) {
            int gl  = tid + h * 512;
            int wn  = gl >> 2;
            int wgi = gl & 3;
            int g   = (noff + wn) * GPR + c * 4 + wgi;
            qr[h] = wq[g];
            nr[h] = cn2[g];
        }
    };

    issueA(0, sb + SM_A0);
    loadW(0);

    uint32_t aoff[2];
#pragma unroll
    for (int mi = 0; mi < 2; mi++)
        aoff[mi] = (uint32_t)(warp_m * 32 + mi * 16 + (lane & 15)) * (K_PAD * 2)
                 + ((lane >> 4) & 1) * 16;
    uint32_t boff[4];
#pragma unroll
    for (int np = 0; np < 4; np++)
        boff[np] = (uint32_t)(warp_n * 64 + np * 16 + ((lane & 7) | ((lane & 16) >> 1))) * (K_PAD * 2)
                 + ((lane >> 3) & 1) * 16;

    const uint32_t MAGIC = 0x64006400u;
    const __half2  magic_h2 = *(const __half2*)&MAGIC;

    for (int c = 0; c < NCHUNK; ++c) {
        const int pb = c & 1;
        const uint32_t abase = sb + (pb ? SM_A1 : SM_A0);
        const uint32_t bbase = sb + (pb ? SM_B1 : SM_B0);

        // ---- dequant + STS B(c)
#pragma unroll
        for (int h = 0; h < 2; h++) {
            int gl  = tid + h * 512;
            int wn  = gl >> 2;
            int wgi = gl & 3;
            __half2 cn = *(__half2*)&nr[h];
            __half2 tc2 = __half2half2(__low2half(cn));    // 2n/3
            __half2 m32 = __half2half2(__high2half(cn));   // -n
            int words[4] = {qr[h].x, qr[h].y, qr[h].z, qr[h].w};
            uint32_t hv[8];
#pragma unroll
            for (int w = 0; w < 4; w++) {
                uint32_t q = (uint32_t)words[w];
                uint32_t u01 = MAGIC | (q & 3u) | ((q & 0xCu) << 14);
                uint32_t u23 = MAGIC | ((q >> 4) & 3u) | ((q & 0xC0u) << 10);
                __half2 v01 = __hsub2(*(__half2*)&u01, magic_h2);
                __half2 v23 = __hsub2(*(__half2*)&u23, magic_h2);
                __half2 w01 = __hfma2(v01, tc2, m32);      // (2n/3)v - n
                __half2 w23 = __hfma2(v23, tc2, m32);
                hv[w * 2]     = *(uint32_t*)&w01;
                hv[w * 2 + 1] = *(uint32_t*)&w23;
            }
            uint32_t a0 = bbase + (uint32_t)wn * (K_PAD * 2) + wgi * 32;
            asm volatile("st.shared.v4.b32 [%0], {%1,%2,%3,%4};"
                :: "r"(a0), "r"(hv[0]), "r"(hv[1]), "r"(hv[2]), "r"(hv[3]) : "memory");
            asm volatile("st.shared.v4.b32 [%0], {%1,%2,%3,%4};"
                :: "r"(a0 + 16), "r"(hv[4]), "r"(hv[5]), "r"(hv[6]), "r"(hv[7]) : "memory");
        }

        CP_WAIT0();
        __syncthreads();

        if (c + 1 < NCHUNK) {
            issueA(c + 1, sb + (pb ? SM_A0 : SM_A1));
            loadW(c + 1);
        }

        // ---- zero f16 span accumulators at span start (span = 2 chunks)
        if ((c & 1) == 0) {
#pragma unroll
            for (int i = 0; i < 2; i++)
#pragma unroll
                for (int j = 0; j < 8; j++) { a16[i][j][0] = 0u; a16[i][j][1] = 0u; }
        }

        // ---- compute chunk c (f16 accumulate)
#pragma unroll
        for (int ks = 0; ks < 4; ++ks) {
            const uint32_t kb = ks * 32;
            uint32_t a0, a1, a2, a3, a4, a5, a6, a7;
            LDSM_X4(a0, a1, a2, a3, abase + aoff[0] + kb);
            LDSM_X4(a4, a5, a6, a7, abase + aoff[1] + kb);
#pragma unroll
            for (int np = 0; np < 4; np++) {
                uint32_t b0, b1, b2, b3;
                LDSM_X4(b0, b1, b2, b3, bbase + boff[np] + kb);
#pragma unroll
                for (int e = 0; e < 2; e++) {
                    int ni = np * 2 + e;
                    uint32_t bb0 = e ? b2 : b0;
                    uint32_t bb1 = e ? b3 : b1;
                    MMA16(a16[0][ni][0], a16[0][ni][1], a0, a1, a2, a3, bb0, bb1);
                    MMA16(a16[1][ni][0], a16[1][ni][1], a4, a5, a6, a7, bb0, bb1);
                }
            }
        }

        // ---- promote span into f32 masters at span end
        if ((c & 1) == 1) {
#pragma unroll
            for (int mi = 0; mi < 2; mi++)
#pragma unroll
                for (int ni = 0; ni < 8; ni++) {
                    float2 lo = __half22float2(*(__half2*)&a16[mi][ni][0]);
                    float2 hi = __half22float2(*(__half2*)&a16[mi][ni][1]);
                    acc[mi][ni][0] += lo.x;
                    acc[mi][ni][1] += lo.y;
                    acc[mi][ni][2] += hi.x;
                    acc[mi][ni][3] += hi.y;
                }
        }
    }

    // ---- epilogue: bias + fp32 store
#pragma unroll
    for (int mi = 0; mi < 2; mi++) {
        int r = moff + warp_m * 32 + mi * 16 + (lane >> 2);
#pragma unroll
        for (int ni = 0; ni < 8; ni++) {
            int ncol = noff + warp_n * 64 + ni * 8 + (lane & 3) * 2;
            float b0 = bias[ncol];
            float b1 = bias[ncol + 1];
            float2* o0 = (float2*)(out + (size_t)r * N_TOT + ncol);
            float2* o1 = (float2*)(out + (size_t)(r + 8) * N_TOT + ncol);
            *o0 = make_float2(acc[mi][ni][0] + b0, acc[mi][ni][1] + b1);
            *o1 = make_float2(acc[mi][ni][2] + b0, acc[mi][ni][3] + b1);
        }
    }
}

// ---------------- launcher ----------------
extern "C" void kernel_launch(void* const* d_in, const int* in_sizes, int n_in,
                              void* d_out, int out_size)
{
    // Bind by size order: wq > norm > x > bias
    int order[4] = {0, 1, 2, 3};
    for (int i = 1; i < 4 && i < n_in; i++) {
        int v = order[i], j = i - 1;
        while (j >= 0 && (long long)in_sizes[order[j]] < (long long)in_sizes[v]) {
            order[j + 1] = order[j]; j--;
        }
        order[j + 1] = v;
    }
    const int4*     wq    = (const int4*)d_in[order[0]];
    const uint16_t* pnorm = (const uint16_t*)d_in[order[1]];
    const float*    x     = (const float*)d_in[order[2]];
    const float*    bias  = (const float*)d_in[order[3]];
    float* out = (float*)d_out;

    prepass<<<NB_NORM + NB_X, 256>>>(pnorm, x);

    uint32_t* cn2_dev = nullptr;
    __half*   xh_dev  = nullptr;
    cudaGetSymbolAddress((void**)&cn2_dev, g_cn2);
    cudaGetSymbolAddress((void**)&xh_dev, g_xh);

    cudaFuncSetAttribute(l2b_hmma, cudaFuncAttributeMaxDynamicSharedMemorySize, SMEM_BYTES);
    dim3 grid(N_TOT / N_TILE, M_TOT / M_TILE);   // (64, 2)
    l2b_hmma<<<grid, THREADS, SMEM_BYTES>>>(wq, cn2_dev, xh_dev, bias, out);
}

// round 7
// speedup vs baseline: 1.5674x; 1.1564x over previous
#include <cuda_runtime.h>
#include <cuda_fp16.h>
#include <cuda_bf16.h>
#include <cstdint>

#define M_TOT 256
#define N_TOT 16384
#define K_TOT 4096
#define G_TOT (N_TOT * K_TOT / 16)   // 4194304
#define GPR   (K_TOT / 16)           // 256 groups per row

#define M_TILE 128
#define N_TILE 128
#define K_CHUNK 64
#define NCHUNK (K_TOT / K_CHUNK)     // 64
#define THREADS 256
#define K_PAD 72                     // halves per row; 144B stride

#define A_BYTES (M_TILE * K_PAD * 2)   // 18432
#define B_BYTES (N_TILE * K_PAD * 2)   // 18432
#define SM_A0 0
#define SM_B0 (SM_A0 + A_BYTES)
#define SM_A1 (SM_B0 + B_BYTES)
#define SM_B1 (SM_A1 + A_BYTES)
#define SMEM_BYTES (SM_B1 + B_BYTES)   // 73728

// prepass grid split
#define NB_NORM 2048
#define NB_X    512

// ---------------- device scratch ----------------
__device__ uint32_t g_cn2[G_TOT];        // half2(2n/3, -n) per group
__device__ __half   g_xh[M_TOT * K_TOT]; // x in fp16

__device__ __forceinline__ uint32_t smem_u32(const void* p) {
    uint32_t a;
    asm("{ .reg .u64 t; cvta.to.shared.u64 t, %1; cvt.u32.u64 %0, t; }" : "=r"(a) : "l"(p));
    return a;
}
#define CP_ASYNC16(dst, src) \
    asm volatile("cp.async.cg.shared.global [%0], [%1], 16;" :: "r"(dst), "l"(src) : "memory")
#define CP_COMMIT() asm volatile("cp.async.commit_group;" ::: "memory")
#define CP_WAIT0()  asm volatile("cp.async.wait_group 0;" ::: "memory")
#define LDSM_X4(r0, r1, r2, r3, a) \
    asm volatile("ldmatrix.sync.aligned.m8n8.x4.shared.b16 {%0,%1,%2,%3}, [%4];" \
        : "=r"(r0), "=r"(r1), "=r"(r2), "=r"(r3) : "r"(a))
#define MMAF32(acc, a0, a1, a2, a3, b0, b1)                                    \
    asm volatile("mma.sync.aligned.m16n8k16.row.col.f32.f16.f16.f32 "          \
        "{%0,%1,%2,%3}, {%4,%5,%6,%7}, {%8,%9}, {%0,%1,%2,%3};\n"              \
        : "+f"((acc)[0]), "+f"((acc)[1]), "+f"((acc)[2]), "+f"((acc)[3])       \
        : "r"(a0), "r"(a1), "r"(a2), "r"(a3), "r"(b0), "r"(b1))

// ---------------- fused prepass ----------------
__global__ void prepass(const uint16_t* __restrict__ pnorm,
                        const float* __restrict__ x)
{
    const int tid = threadIdx.x;
    const int b = blockIdx.x;
    if (b < NB_NORM) {
        const int base = (b * 256 + tid) * 8;
        uint4 raw = *(const uint4*)(pnorm + base);
        uint16_t h[8];
        *(uint4*)h = raw;
        float vh[8], vb[8];
        bool okh = true, okb = true, bigh = false, bigb = false;
#pragma unroll
        for (int i = 0; i < 8; i++) {
            vh[i] = __half2float(*(const __half*)&h[i]);
            vb[i] = __bfloat162float(*(const __nv_bfloat16*)&h[i]);
            okh &= (vh[i] > 1e-6f && vh[i] < 1.0f);
            okb &= (vb[i] > 1e-6f && vb[i] < 1.0f);
            bigh |= (vh[i] > 0.1f);
            bigb |= (vb[i] > 0.1f);
        }
        int allh = __syncthreads_and(okh);
        int allb = __syncthreads_and(okb);
        int anyh = __syncthreads_or(okh && bigh);
        int anyb = __syncthreads_or(okb && bigb);
        uint32_t outw[8];
        if (allh && anyh) {
#pragma unroll
            for (int i = 0; i < 8; i++) {
                __half2 o = __halves2half2(__float2half_rn(vh[i] * (2.0f / 3.0f)),
                                           __float2half_rn(-vh[i]));
                outw[i] = *(uint32_t*)&o;
            }
        } else if (allb && anyb) {
#pragma unroll
            for (int i = 0; i < 8; i++) {
                __half2 o = __halves2half2(__float2half_rn(vb[i] * (2.0f / 3.0f)),
                                           __float2half_rn(-vb[i]));
                outw[i] = *(uint32_t*)&o;
            }
        } else {
            const float* pf = (const float*)pnorm;
#pragma unroll
            for (int i = 0; i < 8; i++) {
                float v = pf[base + i];
                __half2 o = __halves2half2(__float2half_rn(v * (2.0f / 3.0f)),
                                           __float2half_rn(-v));
                outw[i] = *(uint32_t*)&o;
            }
        }
        uint32_t* dst = g_cn2 + base;
        *(uint4*)(dst)     = make_uint4(outw[0], outw[1], outw[2], outw[3]);
        *(uint4*)(dst + 4) = make_uint4(outw[4], outw[5], outw[6], outw[7]);
    } else {
        const int base = ((b - NB_NORM) * 256 + tid) * 8;
        float4 v0 = *(const float4*)(x + base);
        float4 v1 = *(const float4*)(x + base + 4);
        __half2 o[4];
        o[0] = __floats2half2_rn(v0.x, v0.y);
        o[1] = __floats2half2_rn(v0.z, v0.w);
        o[2] = __floats2half2_rn(v1.x, v1.y);
        o[3] = __floats2half2_rn(v1.z, v1.w);
        *(uint4*)(g_xh + base) = *(uint4*)o;
    }
}

// ---------------- main GEMM: 256 thr, tile 128x128, 2 CTAs/SM ----------------
__global__ __launch_bounds__(THREADS, 2)
void l2b_hmma(const int4* __restrict__ wq,
              const uint32_t* __restrict__ cn2,
              const __half* __restrict__ xh,
              const float* __restrict__ bias,
              float* __restrict__ out)
{
    extern __shared__ char smem[];
    const uint32_t sb = smem_u32(smem);
    const int tid  = threadIdx.x;
    const int lane = tid & 31;
    const int warp = tid >> 5;
    const int warp_m = warp >> 2;     // 0..1 : 64 M rows each
    const int warp_n = warp & 3;      // 0..3 : 32 N cols each
    const int noff = blockIdx.x * N_TILE;
    const int moff = blockIdx.y * M_TILE;

    // warp tile 64M x 32N: acc[4 mfrag][4 nfrag][4]
    float acc[4][4][4];
#pragma unroll
    for (int i = 0; i < 4; i++)
#pragma unroll
        for (int j = 0; j < 4; j++)
#pragma unroll
            for (int r = 0; r < 4; r++) acc[i][j][r] = 0.f;

    int4     qr[2];
    uint32_t nr[2];

    // A staging: 1024 16B segs, 4 per thread
    auto issueA = [&](int c, uint32_t abase) {
#pragma unroll
        for (int h = 0; h < 4; h++) {
            int seg = tid + h * 256;
            int row = seg >> 3;
            int s   = seg & 7;
            const __half* src = xh + (size_t)(moff + row) * K_TOT + c * K_CHUNK + s * 8;
            uint32_t dst = abase + row * (K_PAD * 2) + s * 16;
            CP_ASYNC16(dst, src);
        }
        CP_COMMIT();
    };
    // B staging: 512 groups (128 rows x 4), 2 per thread
    auto loadW = [&](int c) {
#pragma unroll
        for (int h = 0; h < 2; h++) {
            int gl  = tid + h * 256;
            int wn  = gl >> 2;
            int wgi = gl & 3;
            int g   = (noff + wn) * GPR + c * 4 + wgi;
            qr[h] = wq[g];
            nr[h] = cn2[g];
        }
    };

    issueA(0, sb + SM_A0);
    loadW(0);

    uint32_t aoff[4];
#pragma unroll
    for (int mi = 0; mi < 4; mi++)
        aoff[mi] = (uint32_t)(warp_m * 64 + mi * 16 + (lane & 15)) * (K_PAD * 2)
                 + ((lane >> 4) & 1) * 16;
    uint32_t boff[2];
#pragma unroll
    for (int np = 0; np < 2; np++)
        boff[np] = (uint32_t)(warp_n * 32 + np * 16 + ((lane & 7) | ((lane & 16) >> 1))) * (K_PAD * 2)
                 + ((lane >> 3) & 1) * 16;

    const uint32_t MAGIC = 0x64006400u;
    const __half2  magic_h2 = *(const __half2*)&MAGIC;

    for (int c = 0; c < NCHUNK; ++c) {
        const int pb = c & 1;
        const uint32_t abase = sb + (pb ? SM_A1 : SM_A0);
        const uint32_t bbase = sb + (pb ? SM_B1 : SM_B0);

        // ---- dequant + STS B(c)
#pragma unroll
        for (int h = 0; h < 2; h++) {
            int gl  = tid + h * 256;
            int wn  = gl >> 2;
            int wgi = gl & 3;
            __half2 cn = *(__half2*)&nr[h];
            __half2 tc2 = __half2half2(__low2half(cn));    // 2n/3
            __half2 m32 = __half2half2(__high2half(cn));   // -n
            int words[4] = {qr[h].x, qr[h].y, qr[h].z, qr[h].w};
            uint32_t hv[8];
#pragma unroll
            for (int w = 0; w < 4; w++) {
                uint32_t q = (uint32_t)words[w];
                uint32_t u01 = MAGIC | (q & 3u) | ((q & 0xCu) << 14);
                uint32_t u23 = MAGIC | ((q >> 4) & 3u) | ((q & 0xC0u) << 10);
                __half2 v01 = __hsub2(*(__half2*)&u01, magic_h2);
                __half2 v23 = __hsub2(*(__half2*)&u23, magic_h2);
                __half2 w01 = __hfma2(v01, tc2, m32);
                __half2 w23 = __hfma2(v23, tc2, m32);
                hv[w * 2]     = *(uint32_t*)&w01;
                hv[w * 2 + 1] = *(uint32_t*)&w23;
            }
            uint32_t a0 = bbase + (uint32_t)wn * (K_PAD * 2) + wgi * 32;
            asm volatile("st.shared.v4.b32 [%0], {%1,%2,%3,%4};"
                :: "r"(a0), "r"(hv[0]), "r"(hv[1]), "r"(hv[2]), "r"(hv[3]) : "memory");
            asm volatile("st.shared.v4.b32 [%0], {%1,%2,%3,%4};"
                :: "r"(a0 + 16), "r"(hv[4]), "r"(hv[5]), "r"(hv[6]), "r"(hv[7]) : "memory");
        }

        CP_WAIT0();
        __syncthreads();

        if (c + 1 < NCHUNK) {
            issueA(c + 1, sb + (pb ? SM_A0 : SM_A1));
            loadW(c + 1);
        }

        // ---- compute chunk c
#pragma unroll
        for (int ks = 0; ks < 4; ++ks) {
            const uint32_t kb = ks * 32;
            uint32_t af[4][4];
#pragma unroll
            for (int mi = 0; mi < 4; mi++)
                LDSM_X4(af[mi][0], af[mi][1], af[mi][2], af[mi][3],
                        abase + aoff[mi] + kb);
#pragma unroll
            for (int np = 0; np < 2; np++) {
                uint32_t b0, b1, b2, b3;
                LDSM_X4(b0, b1, b2, b3, bbase + boff[np] + kb);
#pragma unroll
                for (int e = 0; e < 2; e++) {
                    int ni = np * 2 + e;
                    uint32_t bb0 = e ? b2 : b0;
                    uint32_t bb1 = e ? b3 : b1;
#pragma unroll
                    for (int mi = 0; mi < 4; mi++)
                        MMAF32(acc[mi][ni], af[mi][0], af[mi][1], af[mi][2], af[mi][3],
                               bb0, bb1);
                }
            }
        }
    }

    // ---- epilogue: bias + fp32 store
#pragma unroll
    for (int mi = 0; mi < 4; mi++) {
        int r = moff + warp_m * 64 + mi * 16 + (lane >> 2);
#pragma unroll
        for (int ni = 0; ni < 4; ni++) {
            int ncol = noff + warp_n * 32 + ni * 8 + (lane & 3) * 2;
            float b0 = bias[ncol];
            float b1 = bias[ncol + 1];
            float2* o0 = (float2*)(out + (size_t)r * N_TOT + ncol);
            float2* o1 = (float2*)(out + (size_t)(r + 8) * N_TOT + ncol);
            *o0 = make_float2(acc[mi][ni][0] + b0, acc[mi][ni][1] + b1);
            *o1 = make_float2(acc[mi][ni][2] + b0, acc[mi][ni][3] + b1);
        }
    }
}

// ---------------- launcher ----------------
extern "C" void kernel_launch(void* const* d_in, const int* in_sizes, int n_in,
                              void* d_out, int out_size)
{
    // Bind by size order: wq > norm > x > bias
    int order[4] = {0, 1, 2, 3};
    for (int i = 1; i < 4 && i < n_in; i++) {
        int v = order[i], j = i - 1;
        while (j >= 0 && (long long)in_sizes[order[j]] < (long long)in_sizes[v]) {
            order[j + 1] = order[j]; j--;
        }
        order[j + 1] = v;
    }
    const int4*     wq    = (const int4*)d_in[order[0]];
    const uint16_t* pnorm = (const uint16_t*)d_in[order[1]];
    const float*    x     = (const float*)d_in[order[2]];
    const float*    bias  = (const float*)d_in[order[3]];
    float* out = (float*)d_out;

    prepass<<<NB_NORM + NB_X, 256>>>(pnorm, x);

    uint32_t* cn2_dev = nullptr;
    __half*   xh_dev  = nullptr;
    cudaGetSymbolAddress((void**)&cn2_dev, g_cn2);
    cudaGetSymbolAddress((void**)&xh_dev, g_xh);

    cudaFuncSetAttribute(l2b_hmma, cudaFuncAttributeMaxDynamicSharedMemorySize, SMEM_BYTES);
    dim3 grid(N_TOT / N_TILE, M_TOT / M_TILE);   // (128, 2) = 256 CTAs, 2/SM
    l2b_hmma<<<grid, THREADS, SMEM_BYTES>>>(wq, cn2_dev, xh_dev, bias, out);
}